// round 5
// baseline (speedup 1.0000x reference)
#include <cuda_runtime.h>
#include <cuda_bf16.h>
#include <cstdint>

// ---------------------------------------------------------------------------
// GraphSAGE, 3 layers, mean aggregation. Fully fused per layer:
//   CTA gathers agg tile (mean of h[src] over CSR) into smem (tf32),
//   then dual-A tf32 MMA: out = h@Wself + agg@Wneigh + b (+relu).
// ---------------------------------------------------------------------------

#define MAXN 100000
#define MAXE 1600000
#define SCAN_THREADS 1024

__device__ float g_h1[(size_t)MAXN * 128];
__device__ float g_h2[(size_t)MAXN * 128];
__device__ float g_invdeg[MAXN];
__device__ int   g_degi[MAXN];
__device__ int   g_rowstart[MAXN + 1];
__device__ int   g_cursor[MAXN];
__device__ int   g_colsrc[MAXE];

// ---------------------------------------------------------------------------
// CSR build
// ---------------------------------------------------------------------------
__global__ void count_deg_kernel(const int* __restrict__ dst, int* __restrict__ degi, int E) {
    int i = blockIdx.x * blockDim.x + threadIdx.x;
    if (i < E) atomicAdd(&degi[dst[i]], 1);
}

__global__ void scan_kernel(const int* __restrict__ degi,
                            int* __restrict__ rowstart,
                            float* __restrict__ invdeg, int N) {
    __shared__ int ssum[SCAN_THREADS];
    int t = threadIdx.x;
    int chunk = (N + SCAN_THREADS - 1) / SCAN_THREADS;
    int beg = t * chunk, end = min(N, beg + chunk);

    int s = 0;
    for (int i = beg; i < end; i++) s += degi[i];
    ssum[t] = s;
    __syncthreads();

    for (int off = 1; off < SCAN_THREADS; off <<= 1) {
        int v = (t >= off) ? ssum[t - off] : 0;
        __syncthreads();
        ssum[t] += v;
        __syncthreads();
    }
    int run = ssum[t] - s;
    for (int i = beg; i < end; i++) {
        int d = degi[i];
        rowstart[i] = run;
        invdeg[i] = 1.0f / fmaxf((float)d, 1.0f);
        run += d;
    }
    if (t == SCAN_THREADS - 1) rowstart[N] = run;
}

__global__ void fill_kernel(const int* __restrict__ src,
                            const int* __restrict__ dst,
                            const int* __restrict__ rowstart,
                            int* __restrict__ cursor,
                            int* __restrict__ colsrc, int E) {
    int i = blockIdx.x * blockDim.x + threadIdx.x;
    if (i >= E) return;
    int d = dst[i];
    int pos = rowstart[d] + atomicAdd(&cursor[d], 1);
    colsrc[pos] = src[i];
}

// ---------------------------------------------------------------------------
// tf32 helpers
// ---------------------------------------------------------------------------
__device__ __forceinline__ uint32_t f2tf32(float x) {
    uint32_t u;
    asm("cvt.rna.tf32.f32 %0, %1;" : "=r"(u) : "f"(x));
    return u;
}

__device__ __forceinline__ void mma_tf32(float& c0, float& c1, float& c2, float& c3,
                                         uint32_t a0, uint32_t a1, uint32_t a2, uint32_t a3,
                                         uint32_t b0, uint32_t b1) {
    asm volatile(
        "mma.sync.aligned.m16n8k8.row.col.f32.tf32.tf32.f32 "
        "{%0,%1,%2,%3}, {%4,%5,%6,%7}, {%8,%9}, {%0,%1,%2,%3};\n"
        : "+f"(c0), "+f"(c1), "+f"(c2), "+f"(c3)
        : "r"(a0), "r"(a1), "r"(a2), "r"(a3), "r"(b0), "r"(b1));
}

// ---------------------------------------------------------------------------
// fused layer kernel:
//   out[M,BN] = A[M,128]@W1[128,BN] + agg(A)[M,128]@W2[128,BN] + b (+relu)
// Block 128 rows x BN cols, 256 threads = 8 warps (4m x 2n).
// Phase 1: warp-per-node CSR gather -> As2 (tf32, full 128xK tile in smem)
// Phase 2: K=256 MMA; first 8 stages stream A from global (dbuf),
//          last 8 stages read As2 from smem (no global A traffic).
// ---------------------------------------------------------------------------
template <int BN, bool RELU>
__launch_bounds__(256, 2)
__global__ void sage_layer_kernel(const float* __restrict__ A,
                                  const float* __restrict__ W1,
                                  const float* __restrict__ W2,
                                  const float* __restrict__ bias,
                                  const int* __restrict__ rowstart,
                                  const int* __restrict__ colsrc,
                                  const float* __restrict__ invdeg,
                                  float* __restrict__ out, int M) {
    constexpr int KT   = 16;
    constexpr int NS   = 16;           // total k-stages (8 from A, 8 from As2)
    constexpr int APAD = 4;            // As1 row stride 20
    constexpr int A2S  = 132;          // As2 row stride (128+4), same mod-32 class
    constexpr int BPAD = 8;            // Bs row stride BN+8
    constexpr int NF   = BN / 16;      // n-frags per warp
    constexpr int NB4  = (KT * BN / 4) / 256;   // B float4 loads / thread / stage

    extern __shared__ uint32_t smem[];
    uint32_t (*As1)[128][KT + APAD] = (uint32_t(*)[128][KT + APAD])smem;      // [2]
    uint32_t (*Bs)[KT][BN + BPAD] =
        (uint32_t(*)[KT][BN + BPAD])(smem + 2 * 128 * (KT + APAD));           // [2]
    uint32_t (*As2)[A2S] =
        (uint32_t(*)[A2S])(smem + 2 * 128 * (KT + APAD) + 2 * KT * (BN + BPAD));

    const int tid  = threadIdx.x;
    const int wid  = tid >> 5;
    const int lane = tid & 31;
    const int g    = lane >> 2;      // 0..7
    const int t4   = lane & 3;       // 0..3
    const int warpM = wid & 3;
    const int warpN = wid >> 2;
    const int rowBase = blockIdx.x * 128;

    // ---- issue stage-0 global loads early (complete during gather) ----
    float4 ra[2];
    float4 rb[NB4];
#pragma unroll
    for (int i = 0; i < 2; i++) {
        int f = tid + i * 256;
        int r = f >> 2, kq = f & 3;
        int row = rowBase + r;
        ra[i] = make_float4(0.f, 0.f, 0.f, 0.f);
        if (row < M) ra[i] = *(const float4*)(A + (size_t)row * 128 + kq * 4);
    }
#pragma unroll
    for (int i = 0; i < NB4; i++) {
        int f = tid + i * 256;
        int kk = f / (BN / 4), cc = f % (BN / 4);
        rb[i] = *(const float4*)(W1 + (size_t)kk * BN + cc * 4);
    }

    // ---- phase 1: gather agg tile into As2 (warp per node) ----
    for (int n = wid; n < 128; n += 8) {
        int node = rowBase + n;
        float4 acc = make_float4(0.f, 0.f, 0.f, 0.f);
        if (node < M) {
            int beg = rowstart[node];
            int end = rowstart[node + 1];
            const float* hb = A + lane * 4;
            int j = beg;
            for (; j + 4 <= end; j += 4) {
                int s0 = __ldg(colsrc + j + 0);
                int s1 = __ldg(colsrc + j + 1);
                int s2 = __ldg(colsrc + j + 2);
                int s3 = __ldg(colsrc + j + 3);
                float4 v0 = *(const float4*)(hb + (size_t)s0 * 128);
                float4 v1 = *(const float4*)(hb + (size_t)s1 * 128);
                float4 v2 = *(const float4*)(hb + (size_t)s2 * 128);
                float4 v3 = *(const float4*)(hb + (size_t)s3 * 128);
                acc.x += v0.x + v1.x + v2.x + v3.x;
                acc.y += v0.y + v1.y + v2.y + v3.y;
                acc.z += v0.z + v1.z + v2.z + v3.z;
                acc.w += v0.w + v1.w + v2.w + v3.w;
            }
            for (; j < end; j++) {
                int s = __ldg(colsrc + j);
                float4 v = *(const float4*)(hb + (size_t)s * 128);
                acc.x += v.x; acc.y += v.y; acc.z += v.z; acc.w += v.w;
            }
            float id = invdeg[node];
            acc.x *= id; acc.y *= id; acc.z *= id; acc.w *= id;
        }
        uint4 u;
        u.x = f2tf32(acc.x); u.y = f2tf32(acc.y);
        u.z = f2tf32(acc.z); u.w = f2tf32(acc.w);
        *(uint4*)&As2[n][lane * 4] = u;
    }

    // ---- store stage 0 into buffer 0 ----
#pragma unroll
    for (int i = 0; i < 2; i++) {
        int f = tid + i * 256;
        int r = f >> 2, kq = f & 3;
        uint32_t* p = &As1[0][r][kq * 4];
        p[0] = f2tf32(ra[i].x); p[1] = f2tf32(ra[i].y);
        p[2] = f2tf32(ra[i].z); p[3] = f2tf32(ra[i].w);
    }
#pragma unroll
    for (int i = 0; i < NB4; i++) {
        int f = tid + i * 256;
        int kk = f / (BN / 4), cc = f % (BN / 4);
        uint32_t* p = &Bs[0][kk][cc * 4];
        p[0] = f2tf32(rb[i].x); p[1] = f2tf32(rb[i].y);
        p[2] = f2tf32(rb[i].z); p[3] = f2tf32(rb[i].w);
    }
    __syncthreads();

    float acc[2][NF][4];
#pragma unroll
    for (int mf = 0; mf < 2; mf++)
#pragma unroll
        for (int nf = 0; nf < NF; nf++)
#pragma unroll
            for (int r = 0; r < 4; r++) acc[mf][nf][r] = 0.f;

    // ---- phase 2: 16 k-stages ----
#pragma unroll 1
    for (int s = 0; s < NS; s++) {
        const int buf = s & 1;

        // prefetch stage s+1
        if (s + 1 < NS) {
            const int k0 = ((s + 1) & 7) * KT;
            if (s + 1 < 8) {   // A from global only in first half
#pragma unroll
                for (int i = 0; i < 2; i++) {
                    int f = tid + i * 256;
                    int r = f >> 2, kq = f & 3;
                    int row = rowBase + r;
                    ra[i] = make_float4(0.f, 0.f, 0.f, 0.f);
                    if (row < M) ra[i] = *(const float4*)(A + (size_t)row * 128 + k0 + kq * 4);
                }
            }
            const float* W = (s + 1 < 8) ? W1 : W2;
#pragma unroll
            for (int i = 0; i < NB4; i++) {
                int f = tid + i * 256;
                int kk = f / (BN / 4), cc = f % (BN / 4);
                rb[i] = *(const float4*)(W + (size_t)(k0 + kk) * BN + cc * 4);
            }
        }

        // compute stage s (2 k8-steps)
#pragma unroll
        for (int k8 = 0; k8 < 2; k8++) {
            const int kb = k8 * 8;
            uint32_t a[2][4];
            if (s < 8) {
#pragma unroll
                for (int mf = 0; mf < 2; mf++) {
                    int r0 = warpM * 32 + mf * 16 + g;
                    a[mf][0] = As1[buf][r0][kb + t4];
                    a[mf][1] = As1[buf][r0 + 8][kb + t4];
                    a[mf][2] = As1[buf][r0][kb + t4 + 4];
                    a[mf][3] = As1[buf][r0 + 8][kb + t4 + 4];
                }
            } else {
                const int kc = (s - 8) * KT + kb;
#pragma unroll
                for (int mf = 0; mf < 2; mf++) {
                    int r0 = warpM * 32 + mf * 16 + g;
                    a[mf][0] = As2[r0][kc + t4];
                    a[mf][1] = As2[r0 + 8][kc + t4];
                    a[mf][2] = As2[r0][kc + t4 + 4];
                    a[mf][3] = As2[r0 + 8][kc + t4 + 4];
                }
            }
#pragma unroll
            for (int nf = 0; nf < NF; nf++) {
                int cb = warpN * (BN / 2) + nf * 8 + g;
                uint32_t b0 = Bs[buf][kb + t4][cb];
                uint32_t b1 = Bs[buf][kb + t4 + 4][cb];
#pragma unroll
                for (int mf = 0; mf < 2; mf++) {
                    mma_tf32(acc[mf][nf][0], acc[mf][nf][1],
                             acc[mf][nf][2], acc[mf][nf][3],
                             a[mf][0], a[mf][1], a[mf][2], a[mf][3], b0, b1);
                }
            }
        }

        // store prefetched regs
        if (s + 1 < NS) {
            const int nbuf = buf ^ 1;
            if (s + 1 < 8) {
#pragma unroll
                for (int i = 0; i < 2; i++) {
                    int f = tid + i * 256;
                    int r = f >> 2, kq = f & 3;
                    uint32_t* p = &As1[nbuf][r][kq * 4];
                    p[0] = f2tf32(ra[i].x); p[1] = f2tf32(ra[i].y);
                    p[2] = f2tf32(ra[i].z); p[3] = f2tf32(ra[i].w);
                }
            }
#pragma unroll
            for (int i = 0; i < NB4; i++) {
                int f = tid + i * 256;
                int kk = f / (BN / 4), cc = f % (BN / 4);
                uint32_t* p = &Bs[nbuf][kk][cc * 4];
                p[0] = f2tf32(rb[i].x); p[1] = f2tf32(rb[i].y);
                p[2] = f2tf32(rb[i].z); p[3] = f2tf32(rb[i].w);
            }
            __syncthreads();
        }
    }

    // ---- epilogue ----
#pragma unroll
    for (int nf = 0; nf < NF; nf++) {
        int col = warpN * (BN / 2) + nf * 8 + t4 * 2;
        float2 bv = *(const float2*)(bias + col);
#pragma unroll
        for (int mf = 0; mf < 2; mf++) {
            int r0 = rowBase + warpM * 32 + mf * 16 + g;
            float2 v0 = make_float2(acc[mf][nf][0] + bv.x, acc[mf][nf][1] + bv.y);
            float2 v1 = make_float2(acc[mf][nf][2] + bv.x, acc[mf][nf][3] + bv.y);
            if (RELU) {
                v0.x = fmaxf(v0.x, 0.f); v0.y = fmaxf(v0.y, 0.f);
                v1.x = fmaxf(v1.x, 0.f); v1.y = fmaxf(v1.y, 0.f);
            }
            if (r0 < M)     *(float2*)(out + (size_t)r0 * BN + col)       = v0;
            if (r0 + 8 < M) *(float2*)(out + (size_t)(r0 + 8) * BN + col) = v1;
        }
    }
}

// ---------------------------------------------------------------------------
// launch
// ---------------------------------------------------------------------------
extern "C" void kernel_launch(void* const* d_in, const int* in_sizes, int n_in,
                              void* d_out, int out_size) {
    const float* x   = (const float*)d_in[0];
    const int*   src = (const int*)d_in[1];
    const int*   dst = (const int*)d_in[2];
    const float* Ws0 = (const float*)d_in[3];
    const float* Wn0 = (const float*)d_in[4];
    const float* b0  = (const float*)d_in[5];
    const float* Ws1 = (const float*)d_in[6];
    const float* Wn1 = (const float*)d_in[7];
    const float* b1  = (const float*)d_in[8];
    const float* Ws2 = (const float*)d_in[9];
    const float* Wn2 = (const float*)d_in[10];
    const float* b2  = (const float*)d_in[11];
    float* out = (float*)d_out;

    const int M = in_sizes[0] / 128;   // 100000
    const int E = in_sizes[1];         // 1600000

    float *h1, *h2, *invdeg;
    int *degi, *rowstart, *cursor, *colsrc;
    cudaGetSymbolAddress((void**)&h1,  g_h1);
    cudaGetSymbolAddress((void**)&h2,  g_h2);
    cudaGetSymbolAddress((void**)&invdeg, g_invdeg);
    cudaGetSymbolAddress((void**)&degi, g_degi);
    cudaGetSymbolAddress((void**)&rowstart, g_rowstart);
    cudaGetSymbolAddress((void**)&cursor, g_cursor);
    cudaGetSymbolAddress((void**)&colsrc, g_colsrc);

    // smem sizes: As1(2*128*20) + Bs(2*16*(BN+8)) + As2(128*132), * 4 bytes
    const int SMEM128 = (2 * 128 * 20 + 2 * 16 * 136 + 128 * 132) * 4;  // 105472
    const int SMEM64  = (2 * 128 * 20 + 2 * 16 * 72  + 128 * 132) * 4;  //  97280
    cudaFuncSetAttribute(sage_layer_kernel<128, true>,
                         cudaFuncAttributeMaxDynamicSharedMemorySize, SMEM128);
    cudaFuncSetAttribute(sage_layer_kernel<64, false>,
                         cudaFuncAttributeMaxDynamicSharedMemorySize, SMEM64);

    const int gemmBlocks = (M + 127) / 128;
    const int edgeBlocks = (E + 255) / 256;

    // ---- CSR build (dst-sorted) ----
    cudaMemsetAsync(degi, 0, (size_t)M * sizeof(int));
    cudaMemsetAsync(cursor, 0, (size_t)M * sizeof(int));
    count_deg_kernel<<<edgeBlocks, 256>>>(dst, degi, E);
    scan_kernel<<<1, SCAN_THREADS>>>(degi, rowstart, invdeg, M);
    fill_kernel<<<edgeBlocks, 256>>>(src, dst, rowstart, cursor, colsrc, E);

    // ---- 3 fused layers ----
    sage_layer_kernel<128, true><<<gemmBlocks, 256, SMEM128>>>(
        x, Ws0, Wn0, b0, rowstart, colsrc, invdeg, h1, M);
    sage_layer_kernel<128, true><<<gemmBlocks, 256, SMEM128>>>(
        h1, Ws1, Wn1, b1, rowstart, colsrc, invdeg, h2, M);
    sage_layer_kernel<64, false><<<gemmBlocks, 256, SMEM64>>>(
        h2, Ws2, Wn2, b2, rowstart, colsrc, invdeg, out, M);
}

// round 6
// speedup vs baseline: 1.8720x; 1.8720x over previous
#include <cuda_runtime.h>
#include <cuda_bf16.h>
#include <cstdint>

// ---------------------------------------------------------------------------
// GraphSAGE, 3 layers, mean aggregation. Aggregate-then-transform:
//   agg = mean_{e: dst=d} h[src_e]          (CSR gather, atomic-free)
//   h'  = act([h | agg] @ [Wself; Wneigh] + b)   (dual-A tf32 MMA GEMM, K=256)
// CSR prefix sum is a chip-wide two-level scan (3 tiny kernels).
// ---------------------------------------------------------------------------

#define MAXN 100000
#define MAXE 1600000

__device__ float g_h1[(size_t)MAXN * 128];
__device__ float g_h2[(size_t)MAXN * 128];
__device__ float g_agg[(size_t)MAXN * 128];
__device__ float g_invdeg[MAXN];
__device__ int   g_degi[MAXN];
__device__ int   g_rowstart[MAXN + 1];
__device__ int   g_cursor[MAXN];
__device__ int   g_colsrc[MAXE];
__device__ int   g_blocksum[512];
__device__ int   g_blockoff[512];

// ---------------------------------------------------------------------------
// CSR build
// ---------------------------------------------------------------------------
__global__ void count_deg_kernel(const int* __restrict__ dst, int* __restrict__ degi, int E) {
    int i = blockIdx.x * blockDim.x + threadIdx.x;
    if (i < E) atomicAdd(&degi[dst[i]], 1);
}

// pass 1: per-256-block sums
__global__ void block_reduce_kernel(const int* __restrict__ degi,
                                    int* __restrict__ blocksum, int N) {
    __shared__ int s[256];
    int t = threadIdx.x;
    int i = blockIdx.x * 256 + t;
    s[t] = (i < N) ? degi[i] : 0;
    __syncthreads();
#pragma unroll
    for (int off = 128; off > 0; off >>= 1) {
        if (t < off) s[t] += s[t + off];
        __syncthreads();
    }
    if (t == 0) blocksum[blockIdx.x] = s[0];
}

// pass 2: single block scans the (<=512) block sums -> exclusive offsets
__global__ void scan_blocksums_kernel(const int* __restrict__ blocksum,
                                      int* __restrict__ blockoff, int nb) {
    __shared__ int s[512];
    int t = threadIdx.x;
    int v = (t < nb) ? blocksum[t] : 0;
    s[t] = v;
    __syncthreads();
    for (int off = 1; off < 512; off <<= 1) {
        int u = (t >= off) ? s[t - off] : 0;
        __syncthreads();
        s[t] += u;
        __syncthreads();
    }
    if (t < nb) blockoff[t] = s[t] - v;
}

// pass 3: per-block scan + global offset -> rowstart, invdeg
__global__ void scan_write_kernel(const int* __restrict__ degi,
                                  const int* __restrict__ blockoff,
                                  int* __restrict__ rowstart,
                                  float* __restrict__ invdeg, int N) {
    __shared__ int s[256];
    int t = threadIdx.x;
    int i = blockIdx.x * 256 + t;
    int v = (i < N) ? degi[i] : 0;
    s[t] = v;
    __syncthreads();
    for (int off = 1; off < 256; off <<= 1) {
        int u = (t >= off) ? s[t - off] : 0;
        __syncthreads();
        s[t] += u;
        __syncthreads();
    }
    if (i < N) {
        int excl = s[t] - v + blockoff[blockIdx.x];
        rowstart[i] = excl;
        invdeg[i] = 1.0f / fmaxf((float)v, 1.0f);
        if (i == N - 1) rowstart[N] = excl + v;
    }
}

__global__ void fill_kernel(const int* __restrict__ src,
                            const int* __restrict__ dst,
                            const int* __restrict__ rowstart,
                            int* __restrict__ cursor,
                            int* __restrict__ colsrc, int E) {
    int i = blockIdx.x * blockDim.x + threadIdx.x;
    if (i >= E) return;
    int d = dst[i];
    int pos = rowstart[d] + atomicAdd(&cursor[d], 1);
    colsrc[pos] = src[i];
}

// ---------------------------------------------------------------------------
// gather: agg[n] = inv_deg[n] * sum_{j in row(n)} h[colsrc[j]]   (warp/node)
// ---------------------------------------------------------------------------
__global__ void gather_kernel(const float* __restrict__ h,
                              const int* __restrict__ rowstart,
                              const int* __restrict__ colsrc,
                              const float* __restrict__ invdeg,
                              float* __restrict__ agg, int N) {
    int warp = (blockIdx.x * blockDim.x + threadIdx.x) >> 5;
    int lane = threadIdx.x & 31;
    if (warp >= N) return;
    int beg = rowstart[warp];
    int end = rowstart[warp + 1];

    const float* hb = h + lane * 4;
    float4 acc = make_float4(0.f, 0.f, 0.f, 0.f);
    int j = beg;
    for (; j + 4 <= end; j += 4) {
        int s0 = __ldg(colsrc + j + 0);
        int s1 = __ldg(colsrc + j + 1);
        int s2 = __ldg(colsrc + j + 2);
        int s3 = __ldg(colsrc + j + 3);
        float4 v0 = *(const float4*)(hb + (size_t)s0 * 128);
        float4 v1 = *(const float4*)(hb + (size_t)s1 * 128);
        float4 v2 = *(const float4*)(hb + (size_t)s2 * 128);
        float4 v3 = *(const float4*)(hb + (size_t)s3 * 128);
        acc.x += v0.x + v1.x + v2.x + v3.x;
        acc.y += v0.y + v1.y + v2.y + v3.y;
        acc.z += v0.z + v1.z + v2.z + v3.z;
        acc.w += v0.w + v1.w + v2.w + v3.w;
    }
    for (; j < end; j++) {
        int s = __ldg(colsrc + j);
        float4 v = *(const float4*)(hb + (size_t)s * 128);
        acc.x += v.x; acc.y += v.y; acc.z += v.z; acc.w += v.w;
    }
    float id = invdeg[warp];
    acc.x *= id; acc.y *= id; acc.z *= id; acc.w *= id;
    *(float4*)(agg + (size_t)warp * 128 + lane * 4) = acc;
}

// ---------------------------------------------------------------------------
// tf32 helpers
// ---------------------------------------------------------------------------
__device__ __forceinline__ uint32_t f2tf32(float x) {
    uint32_t u;
    asm("cvt.rna.tf32.f32 %0, %1;" : "=r"(u) : "f"(x));
    return u;
}

__device__ __forceinline__ void mma_tf32(float& c0, float& c1, float& c2, float& c3,
                                         uint32_t a0, uint32_t a1, uint32_t a2, uint32_t a3,
                                         uint32_t b0, uint32_t b1) {
    asm volatile(
        "mma.sync.aligned.m16n8k8.row.col.f32.tf32.tf32.f32 "
        "{%0,%1,%2,%3}, {%4,%5,%6,%7}, {%8,%9}, {%0,%1,%2,%3};\n"
        : "+f"(c0), "+f"(c1), "+f"(c2), "+f"(c3)
        : "r"(a0), "r"(a1), "r"(a2), "r"(a3), "r"(b0), "r"(b1));
}

// ---------------------------------------------------------------------------
// dual-A tf32 GEMM:  out[M,BN] = A1[M,128]@W1[128,BN] + A2[M,128]@W2[128,BN]+b
// Block 128 x BN, 256 threads = 8 warps (4m x 2n), warp tile 32 x BN/2.
// mma m16n8k8 tf32, K tiled at KT=16, double-buffered, register prefetch.
// ---------------------------------------------------------------------------
template <int BN, bool RELU>
__launch_bounds__(256, 2)
__global__ void gemm_tc_kernel(const float* __restrict__ A1,
                               const float* __restrict__ A2,
                               const float* __restrict__ W1,
                               const float* __restrict__ W2,
                               const float* __restrict__ bias,
                               float* __restrict__ out, int M) {
    constexpr int KT  = 16;
    constexpr int NS  = 16;            // 256 / KT
    constexpr int APAD = 4;            // A row stride 20 -> conflict-free frags
    constexpr int BPAD = 8;            // B row stride BN+8 (== 8 mod 32)
    constexpr int NF  = BN / 16;       // n-frags per warp (warp n-extent BN/2)
    constexpr int NB4 = (KT * BN / 4) / 256;   // B float4 loads / thread / stage

    __shared__ uint32_t As[2][128][KT + APAD];
    __shared__ uint32_t Bs[2][KT][BN + BPAD];

    const int tid  = threadIdx.x;
    const int wid  = tid >> 5;
    const int lane = tid & 31;
    const int g    = lane >> 2;      // 0..7
    const int t4   = lane & 3;       // 0..3
    const int warpM = wid & 3;       // 0..3  (32-row slice)
    const int warpN = wid >> 2;      // 0..1  (BN/2-col slice)
    const int rowBase = blockIdx.x * 128;

    float acc[2][NF][4];
#pragma unroll
    for (int mf = 0; mf < 2; mf++)
#pragma unroll
        for (int nf = 0; nf < NF; nf++)
#pragma unroll
            for (int r = 0; r < 4; r++) acc[mf][nf][r] = 0.f;

    float4 ra[2];
    float4 rb[NB4];

    // ---- prologue: stage 0 (A1 / W1, k0 = 0) ----
    {
#pragma unroll
        for (int i = 0; i < 2; i++) {
            int f = tid + i * 256;               // 0..511
            int r = f >> 2, kq = f & 3;
            int row = rowBase + r;
            float4 v = make_float4(0.f, 0.f, 0.f, 0.f);
            if (row < M) v = *(const float4*)(A1 + (size_t)row * 128 + kq * 4);
            uint32_t* p = &As[0][r][kq * 4];
            p[0] = f2tf32(v.x); p[1] = f2tf32(v.y);
            p[2] = f2tf32(v.z); p[3] = f2tf32(v.w);
        }
#pragma unroll
        for (int i = 0; i < NB4; i++) {
            int f = tid + i * 256;
            int kk = f / (BN / 4), cc = f % (BN / 4);
            float4 v = *(const float4*)(W1 + (size_t)kk * BN + cc * 4);
            uint32_t* p = &Bs[0][kk][cc * 4];
            p[0] = f2tf32(v.x); p[1] = f2tf32(v.y);
            p[2] = f2tf32(v.z); p[3] = f2tf32(v.w);
        }
    }
    __syncthreads();

    // ---- main loop over 16 stages ----
#pragma unroll 1
    for (int s = 0; s < NS; s++) {
        const int buf = s & 1;

        // prefetch stage s+1 into registers
        if (s + 1 < NS) {
            const float* A = (s + 1 < 8) ? A1 : A2;
            const float* W = (s + 1 < 8) ? W1 : W2;
            const int k0 = ((s + 1) & 7) * KT;
#pragma unroll
            for (int i = 0; i < 2; i++) {
                int f = tid + i * 256;
                int r = f >> 2, kq = f & 3;
                int row = rowBase + r;
                ra[i] = make_float4(0.f, 0.f, 0.f, 0.f);
                if (row < M) ra[i] = *(const float4*)(A + (size_t)row * 128 + k0 + kq * 4);
            }
#pragma unroll
            for (int i = 0; i < NB4; i++) {
                int f = tid + i * 256;
                int kk = f / (BN / 4), cc = f % (BN / 4);
                rb[i] = *(const float4*)(W + (size_t)(k0 + kk) * BN + cc * 4);
            }
        }

        // compute: 2 k8-steps on buf
#pragma unroll
        for (int k8 = 0; k8 < 2; k8++) {
            const int kb = k8 * 8;
            uint32_t a[2][4];
#pragma unroll
            for (int mf = 0; mf < 2; mf++) {
                int r0 = warpM * 32 + mf * 16 + g;
                a[mf][0] = As[buf][r0][kb + t4];
                a[mf][1] = As[buf][r0 + 8][kb + t4];
                a[mf][2] = As[buf][r0][kb + t4 + 4];
                a[mf][3] = As[buf][r0 + 8][kb + t4 + 4];
            }
#pragma unroll
            for (int nf = 0; nf < NF; nf++) {
                int cb = warpN * (BN / 2) + nf * 8 + g;
                uint32_t b0 = Bs[buf][kb + t4][cb];
                uint32_t b1 = Bs[buf][kb + t4 + 4][cb];
#pragma unroll
                for (int mf = 0; mf < 2; mf++) {
                    mma_tf32(acc[mf][nf][0], acc[mf][nf][1],
                             acc[mf][nf][2], acc[mf][nf][3],
                             a[mf][0], a[mf][1], a[mf][2], a[mf][3], b0, b1);
                }
            }
        }

        // store prefetched regs into other buffer
        if (s + 1 < NS) {
            const int nbuf = buf ^ 1;
#pragma unroll
            for (int i = 0; i < 2; i++) {
                int f = tid + i * 256;
                int r = f >> 2, kq = f & 3;
                uint32_t* p = &As[nbuf][r][kq * 4];
                p[0] = f2tf32(ra[i].x); p[1] = f2tf32(ra[i].y);
                p[2] = f2tf32(ra[i].z); p[3] = f2tf32(ra[i].w);
            }
#pragma unroll
            for (int i = 0; i < NB4; i++) {
                int f = tid + i * 256;
                int kk = f / (BN / 4), cc = f % (BN / 4);
                uint32_t* p = &Bs[nbuf][kk][cc * 4];
                p[0] = f2tf32(rb[i].x); p[1] = f2tf32(rb[i].y);
                p[2] = f2tf32(rb[i].z); p[3] = f2tf32(rb[i].w);
            }
            __syncthreads();
        }
    }

    // ---- epilogue: bias (+relu), write float2 per frag-row ----
#pragma unroll
    for (int nf = 0; nf < NF; nf++) {
        int col = warpN * (BN / 2) + nf * 8 + t4 * 2;
        float2 bv = *(const float2*)(bias + col);
#pragma unroll
        for (int mf = 0; mf < 2; mf++) {
            int r0 = rowBase + warpM * 32 + mf * 16 + g;
            float2 v0 = make_float2(acc[mf][nf][0] + bv.x, acc[mf][nf][1] + bv.y);
            float2 v1 = make_float2(acc[mf][nf][2] + bv.x, acc[mf][nf][3] + bv.y);
            if (RELU) {
                v0.x = fmaxf(v0.x, 0.f); v0.y = fmaxf(v0.y, 0.f);
                v1.x = fmaxf(v1.x, 0.f); v1.y = fmaxf(v1.y, 0.f);
            }
            if (r0 < M)     *(float2*)(out + (size_t)r0 * BN + col)       = v0;
            if (r0 + 8 < M) *(float2*)(out + (size_t)(r0 + 8) * BN + col) = v1;
        }
    }
}

// ---------------------------------------------------------------------------
// launch
// ---------------------------------------------------------------------------
extern "C" void kernel_launch(void* const* d_in, const int* in_sizes, int n_in,
                              void* d_out, int out_size) {
    const float* x   = (const float*)d_in[0];
    const int*   src = (const int*)d_in[1];
    const int*   dst = (const int*)d_in[2];
    const float* Ws0 = (const float*)d_in[3];
    const float* Wn0 = (const float*)d_in[4];
    const float* b0  = (const float*)d_in[5];
    const float* Ws1 = (const float*)d_in[6];
    const float* Wn1 = (const float*)d_in[7];
    const float* b1  = (const float*)d_in[8];
    const float* Ws2 = (const float*)d_in[9];
    const float* Wn2 = (const float*)d_in[10];
    const float* b2  = (const float*)d_in[11];
    float* out = (float*)d_out;

    const int M = in_sizes[0] / 128;   // 100000
    const int E = in_sizes[1];         // 1600000

    float *h1, *h2, *agg, *invdeg;
    int *degi, *rowstart, *cursor, *colsrc, *blocksum, *blockoff;
    cudaGetSymbolAddress((void**)&h1,  g_h1);
    cudaGetSymbolAddress((void**)&h2,  g_h2);
    cudaGetSymbolAddress((void**)&agg, g_agg);
    cudaGetSymbolAddress((void**)&invdeg, g_invdeg);
    cudaGetSymbolAddress((void**)&degi, g_degi);
    cudaGetSymbolAddress((void**)&rowstart, g_rowstart);
    cudaGetSymbolAddress((void**)&cursor, g_cursor);
    cudaGetSymbolAddress((void**)&colsrc, g_colsrc);
    cudaGetSymbolAddress((void**)&blocksum, g_blocksum);
    cudaGetSymbolAddress((void**)&blockoff, g_blockoff);

    const int gemmBlocks   = (M + 127) / 128;
    const int edgeBlocks   = (E + 255) / 256;
    const int gatherBlocks = (M * 32 + 255) / 256;   // warp per node
    const int scanBlocks   = (M + 255) / 256;        // 391

    // ---- CSR build (dst-sorted) ----
    cudaMemsetAsync(degi, 0, (size_t)M * sizeof(int));
    cudaMemsetAsync(cursor, 0, (size_t)M * sizeof(int));
    count_deg_kernel<<<edgeBlocks, 256>>>(dst, degi, E);
    block_reduce_kernel<<<scanBlocks, 256>>>(degi, blocksum, M);
    scan_blocksums_kernel<<<1, 512>>>(blocksum, blockoff, scanBlocks);
    scan_write_kernel<<<scanBlocks, 256>>>(degi, blockoff, rowstart, invdeg, M);
    fill_kernel<<<edgeBlocks, 256>>>(src, dst, rowstart, cursor, colsrc, E);

    // ---- layer 0: h1 = relu(x@Ws0 + agg(x)@Wn0 + b0) ----
    gather_kernel<<<gatherBlocks, 256>>>(x, rowstart, colsrc, invdeg, agg, M);
    gemm_tc_kernel<128, true><<<gemmBlocks, 256>>>(x, agg, Ws0, Wn0, b0, h1, M);

    // ---- layer 1 ----
    gather_kernel<<<gatherBlocks, 256>>>(h1, rowstart, colsrc, invdeg, agg, M);
    gemm_tc_kernel<128, true><<<gemmBlocks, 256>>>(h1, agg, Ws1, Wn1, b1, h2, M);

    // ---- layer 2 (no relu, BN=64) ----
    gather_kernel<<<gatherBlocks, 256>>>(h2, rowstart, colsrc, invdeg, agg, M);
    gemm_tc_kernel<64, false><<<gemmBlocks, 256>>>(h2, agg, Ws2, Wn2, b2, out, M);
}